// round 16
// baseline (speedup 1.0000x reference)
#include <cuda_runtime.h>
#include <math.h>
#include <stdint.h>

#define IN_DIM 512
#define HID    1024
#define MEMD   1024
#define OUTD   512
#define BATCH  4096

#define TM 128
#define TN 128
#define KC 32
#define GEMM_THREADS 256
#define CH_FLOATS (128 * 32)
#define CH_BYTES  (CH_FLOATS * 4)            // 16384
#define SMEM_BYTES_G (6 * CH_BYTES)          // 98304, 2 CTAs/SM
#define GEMM_GRID 296

#define VB 64                                // recurrence blocks (own barrier)
#define VTHREADS 256

// ---------------- device scratch ----------------
__device__ __align__(16) float g_xT [(size_t)BATCH * IN_DIM];
__device__ __align__(16) float g_pre[3][(size_t)BATCH * HID];
__device__ __align__(16) float g_rgm[(size_t)BATCH * MEMD];
__device__ __align__(16) float g_hid[(size_t)BATCH * HID];

// vector state
__device__ __align__(16) float g_out_v[OUTD];
__device__ __align__(16) float g_mem_v[MEMD];
__device__ __align__(16) float g_prod_v[HID];
__device__ __align__(16) float g_rgmem_v[MEMD];
__device__ __align__(16) float g_wg_v[MEMD];
__device__ __align__(16) float g_hid_v[HID];
__device__ __align__(16) float g_c_inp[HID];
__device__ __align__(16) float g_c_ig[HID];
__device__ __align__(16) float g_c_rg[MEMD];

// software grid barrier for k_vec (g_cnt returns to 0; g_gen monotonic)
__device__ unsigned g_cnt = 0;
__device__ unsigned g_gen = 0;
__device__ unsigned g_vdone = 0;             // k_vec completion flag (reset each replay)

struct P {
    const float *input;
    const float *W_ig, *b_ig, *W_rig, *b_rig, *W_mig, *b_mig;
    const float *W_inp, *b_inp, *W_rinp, *b_rinp;
    const float *W_rg, *b_rg, *W_rrg, *b_rrg, *W_mrg, *b_mrg;
    const float *W_dec, *b_dec;
    const float *W_wg, *b_wg, *W_rwg, *b_rwg, *W_mwg, *b_mwg;
    const float *W_enc, *b_enc, *w_ho;
};

// ---- fast activations: HW tanh.approx ----
__device__ __forceinline__ float tanh_ap(float x) {
    float y;
    asm("tanh.approx.f32 %0, %1;" : "=f"(y) : "f"(x));
    return y;
}
__device__ __forceinline__ float sigf(float x) {
    return fmaf(0.5f, tanh_ap(0.5f * x), 0.5f);
}
__device__ __forceinline__ float warp_sum(float v) {
    #pragma unroll
    for (int o = 16; o; o >>= 1) v += __shfl_xor_sync(0xFFFFFFFFu, v, o);
    return v;
}
__device__ __forceinline__ float dot4(float4 a, float4 b) {
    return a.x * b.x + a.y * b.y + a.z * b.z + a.w * b.w;
}

__device__ __forceinline__ void mma1688(float* c, const uint32_t* a, const uint32_t* b) {
    asm volatile(
        "mma.sync.aligned.m16n8k8.row.col.f32.tf32.tf32.f32 "
        "{%0,%1,%2,%3}, {%4,%5,%6,%7}, {%8,%9}, {%0,%1,%2,%3};"
        : "+f"(c[0]), "+f"(c[1]), "+f"(c[2]), "+f"(c[3])
        : "r"(a[0]), "r"(a[1]), "r"(a[2]), "r"(a[3]), "r"(b[0]), "r"(b[1]));
}
__device__ __forceinline__ void ldsm4(uint32_t* r, uint32_t addr) {
    asm volatile("ldmatrix.sync.aligned.m8n8.x4.shared.b16 {%0,%1,%2,%3}, [%4];"
        : "=r"(r[0]), "=r"(r[1]), "=r"(r[2]), "=r"(r[3]) : "r"(addr));
}
__device__ __forceinline__ void cp16(uint32_t dst, const void* src) {
    asm volatile("cp.async.cg.shared.global [%0], [%1], 16;" :: "r"(dst), "l"(src));
}
#define CP_COMMIT() asm volatile("cp.async.commit_group;" ::: "memory")
#define CP_WAIT(n)  asm volatile("cp.async.wait_group %0;" :: "n"(n) : "memory")
__device__ __forceinline__ uint32_t smem_u32(const void* p) {
    uint32_t a;
    asm("{ .reg .u64 t; cvta.to.shared.u64 t, %1; cvt.u32.u64 %0, t; }" : "=r"(a) : "l"(p));
    return a;
}

// ---------------- grid barrier over VB co-resident blocks ----------------
__device__ __forceinline__ void gsync(unsigned* mygen) {
    __syncthreads();
    if (threadIdx.x == 0) {
        __threadfence();
        unsigned a = atomicAdd(&g_cnt, 1);
        if (a == VB - 1) {
            g_cnt = 0;
            __threadfence();
            atomicAdd(&g_gen, 1);
        } else {
            while (*(volatile unsigned*)&g_gen == *mygen) __nanosleep(64);
        }
        __threadfence();
    }
    __syncthreads();
    (*mygen)++;
}

// ---------------- reset: clears completion flag (strictly before k_vec & stage-1) ----------------
__global__ void k_reset() {
    if (threadIdx.x == 0) g_vdone = 0;
}

// ---------------- transpose: input [512,4096] -> g_xT [4096,512] ----------------
__global__ void k_transpose(const float* __restrict__ in) {
    __shared__ float t[32][33];
    int bx = blockIdx.x * 32;
    int by = blockIdx.y * 32;
    for (int j = threadIdx.y; j < 32; j += 8)
        t[j][threadIdx.x] = in[(size_t)(by + j) * BATCH + bx + threadIdx.x];
    __syncthreads();
    for (int j = threadIdx.y; j < 32; j += 8)
        g_xT[(size_t)(bx + j) * IN_DIM + by + threadIdx.x] = t[threadIdx.x][j];
}

// ---------------- persistent vector recurrence (VB blocks; runs ∥ stage-1) ----------------
__global__ __launch_bounds__(VTHREADS) void k_vec(P p) {
    const int tid = threadIdx.x, wid = tid >> 5, lane = tid & 31;
    const int gw = blockIdx.x * (VTHREADS / 32) + wid;
    const int VW = VB * (VTHREADS / 32);
    unsigned mygen = *(volatile unsigned*)&g_gen;

    // ---- step 0 elementwise: out=mem=0 -> gates are bias-only ----
    for (int h = blockIdx.x * VTHREADS + tid; h < HID; h += VB * VTHREADS) {
        float pbi = p.b_inp[h] + p.b_rinp[h];
        float pig = p.b_ig[h] + p.b_mig[h] + p.b_rig[h];
        float pwg = p.b_wg[h] + p.b_mwg[h] + p.b_rwg[h];
        __stcg(&g_hid_v[h], p.b_dec[h] + sigf(pbi) * sigf(pig));
        __stcg(&g_wg_v[h], sigf(pwg));
    }
    gsync(&mygen);

    auto do_update = [&](bool first) {
        for (int r = gw; r < MEMD + OUTD; r += VW) {
            const float* W = (r < MEMD) ? (p.W_enc + (size_t)r * HID)
                                        : (p.w_ho + (size_t)(r - MEMD) * HID);
            float s = 0.f;
            #pragma unroll
            for (int j = 0; j < 8; j++) {
                int k = lane + j * 32;
                float4 hv = __ldcg((const float4*)g_hid_v + k);
                s += dot4(hv, *((const float4*)W + k));
            }
            s = warp_sum(s);
            if (lane == 0) {
                if (r < MEMD) {
                    float e = tanh_ap(s + p.b_enc[r]);
                    float w = __ldcg(&g_wg_v[r]);
                    float m = first ? (w * e) : ((1.0f - w) * __ldcg(&g_mem_v[r]) + w * e);
                    __stcg(&g_mem_v[r], m);
                } else {
                    __stcg(&g_out_v[r - MEMD], s);
                }
            }
        }
    };

    do_update(true);
    gsync(&mygen);

    auto do_gates = [&](bool constants) {
        for (int h = gw; h < HID; h += VW) {
            const float4* Wbi = (const float4*)(p.W_rinp + (size_t)h * OUTD);
            const float4* Wig = (const float4*)(p.W_rig  + (size_t)h * OUTD);
            const float4* Wrg = (const float4*)(p.W_rrg  + (size_t)h * OUTD);
            const float4* Wwg = (const float4*)(p.W_rwg  + (size_t)h * OUTD);
            const float4* Mig = (const float4*)(p.W_mig  + (size_t)h * MEMD);
            const float4* Mrg = (const float4*)(p.W_mrg  + (size_t)h * MEMD);
            const float4* Mwg = (const float4*)(p.W_mwg  + (size_t)h * MEMD);
            float s_bi = 0.f, s_ig = 0.f, s_rg = 0.f, s_wg = 0.f;
            #pragma unroll
            for (int j = 0; j < 4; j++) {
                int k = lane + j * 32;
                float4 o = __ldcg((const float4*)g_out_v + k);
                s_bi += dot4(o, Wbi[k]);
                s_ig += dot4(o, Wig[k]);
                s_rg += dot4(o, Wrg[k]);
                if (!constants) s_wg += dot4(o, Wwg[k]);
            }
            #pragma unroll
            for (int j = 0; j < 8; j++) {
                int k = lane + j * 32;
                float4 m = __ldcg((const float4*)g_mem_v + k);
                s_ig += dot4(m, Mig[k]);
                s_rg += dot4(m, Mrg[k]);
                if (!constants) s_wg += dot4(m, Mwg[k]);
            }
            s_bi = warp_sum(s_bi); s_ig = warp_sum(s_ig); s_rg = warp_sum(s_rg);
            if (!constants) s_wg = warp_sum(s_wg);
            if (lane == 0) {
                float pbi = s_bi + p.b_inp[h] + p.b_rinp[h];
                float pig = s_ig + p.b_ig[h] + p.b_mig[h] + p.b_rig[h];
                float prg = s_rg + p.b_rg[h] + p.b_mrg[h] + p.b_rrg[h];
                if (!constants) {
                    float pwg = s_wg + p.b_wg[h] + p.b_mwg[h] + p.b_rwg[h];
                    __stcg(&g_prod_v[h],  sigf(pbi) * sigf(pig));
                    __stcg(&g_rgmem_v[h], sigf(prg) * __ldcg(&g_mem_v[h]));
                    __stcg(&g_wg_v[h],    sigf(pwg));
                } else {
                    __stcg(&g_c_inp[h], pbi);
                    __stcg(&g_c_ig[h],  pig);
                    __stcg(&g_c_rg[h],  prg);
                }
            }
        }
    };

    for (int s = 1; s <= 3; s++) {
        do_gates(false);
        gsync(&mygen);
        for (int h = gw; h < HID; h += VW) {
            const float4* Wd = (const float4*)(p.W_dec + (size_t)h * MEMD);
            float s2 = 0.f;
            #pragma unroll
            for (int j = 0; j < 8; j++) {
                int k = lane + j * 32;
                float4 rg = __ldcg((const float4*)g_rgmem_v + k);
                s2 += dot4(rg, Wd[k]);
            }
            s2 = warp_sum(s2);
            if (lane == 0)
                __stcg(&g_hid_v[h], s2 + p.b_dec[h] + __ldcg(&g_prod_v[h]));
        }
        gsync(&mygen);
        do_update(false);
        gsync(&mygen);
    }

    do_gates(true);   // step-4 batch-uniform constants
    gsync(&mygen);    // all constants written + fenced
    if (blockIdx.x == 0 && tid == 0) atomicExch(&g_vdone, 1u);
}

// ---------------- fused stage-1 + gate: 1 CTA per (mb,nb), 3 sequential GEMMs ----------------
// mat0/mat1: store pre raw. mat2 epilogue: prod = sig(pre0+ci)*sig(pre1+cg) -> pre0,
// rgm = sig(acc2+cr)*mem_v. Waits on g_vdone (k_vec) before the fused epilogue.
__global__ __launch_bounds__(GEMM_THREADS, 2) void k_s1(P p) {
    extern __shared__ float smem[];
    const uint32_t smb = smem_u32(smem);
    const int tid = threadIdx.x, wid = tid >> 5, lane = tid & 31;
    const int g = lane >> 2, t4 = lane & 3;
    const int wm = (wid >> 2) * 64, wn = (wid & 3) * 32;
    const int m0 = (blockIdx.x >> 3) * TM, n0 = (blockIdx.x & 7) * TN;

    const int ld_r0 = tid >> 3;
    const int ld_q = tid & 7;
    const int jm = lane >> 3, rr = lane & 7;
    const int hA = jm >> 1, hB = jm & 1;
    const uint32_t aRowOff = (uint32_t)(wm + (jm & 1) * 8 + rr) * 128u;
    const uint32_t bRowOff = (uint32_t)(wn + (jm >> 1) * 8 + rr) * 128u;

    #pragma unroll 1
    for (int mat = 0; mat < 3; mat++) {
        const float* B = (mat == 0) ? p.W_inp : ((mat == 1) ? p.W_ig : p.W_rg);

        float acc[4][4][4];
        #pragma unroll
        for (int i = 0; i < 4; i++)
            #pragma unroll
            for (int j = 0; j < 4; j++)
                #pragma unroll
                for (int q = 0; q < 4; q++) acc[i][j][q] = 0.f;

        auto issue = [&](int k0, int buf) {
            uint32_t ab = smb + buf * CH_BYTES;
            uint32_t bb = smb + (3 + buf) * CH_BYTES;
            #pragma unroll
            for (int j = 0; j < 4; j++) {
                int r = ld_r0 + j * 32;
                uint32_t dst = (uint32_t)((r * 8 + (ld_q ^ (r & 7))) * 16);
                cp16(ab + dst, g_xT + (size_t)(m0 + r) * IN_DIM + k0 + ld_q * 4);
                cp16(bb + dst, B + (size_t)(n0 + r) * IN_DIM + k0 + ld_q * 4);
            }
            CP_COMMIT();
        };
        auto compute = [&](int buf) {
            const uint32_t abase = smb + buf * CH_BYTES + aRowOff;
            const uint32_t bbase = smb + (3 + buf) * CH_BYTES + bRowOff;
            #pragma unroll
            for (int ks = 0; ks < 4; ks++) {
                const uint32_t qa = (uint32_t)(((2 * ks + hA) ^ rr) << 4);
                const uint32_t qb = (uint32_t)(((2 * ks + hB) ^ rr) << 4);
                uint32_t af[4][4], bf[8];
                #pragma unroll
                for (int mt = 0; mt < 4; mt++)
                    ldsm4(af[mt], abase + (uint32_t)(mt * 2048) + qa);
                ldsm4(bf,     bbase + qb);
                ldsm4(bf + 4, bbase + 2048u + qb);
                #pragma unroll
                for (int mt = 0; mt < 4; mt++)
                    #pragma unroll
                    for (int nt = 0; nt < 4; nt++)
                        mma1688(acc[mt][nt], af[mt], bf + nt * 2);
            }
        };

        const int nc = IN_DIM / KC;   // 16
        issue(0, 0);
        issue(KC, 1);
        for (int c = 0; c < nc; c++) {
            CP_WAIT(1);
            __syncthreads();
            if (c + 2 < nc) issue((c + 2) * KC, (c + 2) % 3);
            compute(c % 3);
        }
        __syncthreads();

        // ---- stage acc to smem ----
        float* stg = smem;
        #pragma unroll
        for (int mt = 0; mt < 4; mt++) {
            #pragma unroll
            for (int nt = 0; nt < 4; nt++) {
                int rrow = wm + mt * 16 + g;
                int cc = wn + nt * 8 + t4 * 2;
                *(float2*)(stg + rrow * 132 + cc)       = make_float2(acc[mt][nt][0], acc[mt][nt][1]);
                *(float2*)(stg + (rrow + 8) * 132 + cc) = make_float2(acc[mt][nt][2], acc[mt][nt][3]);
            }
        }

        if (mat < 2) {
            __syncthreads();
            float* C = &g_pre[mat][0];
            #pragma unroll
            for (int j = 0; j < 16; j++) {
                int s = j * GEMM_THREADS + tid;
                int r = s >> 5, cq = s & 31;
                *(float4*)(C + (size_t)(m0 + r) * HID + n0 + cq * 4) =
                    *(float4*)(stg + r * 132 + cq * 4);
            }
            __syncthreads();
        } else {
            // wait for k_vec constants (typically already done)
            if (tid == 0) {
                while (*(volatile unsigned*)&g_vdone == 0u) __nanosleep(128);
                __threadfence();
            }
            __syncthreads();
            // fused gate epilogue
            #pragma unroll
            for (int j = 0; j < 16; j++) {
                int s = j * GEMM_THREADS + tid;
                int r = s >> 5, cq = s & 31;
                int m = m0 + r, n = n0 + cq * 4;
                size_t off = (size_t)m * HID + n;
                float4 pr = *(float4*)(stg + r * 132 + cq * 4);       // pre_rg
                float4 pi = *(const float4*)&g_pre[0][off];           // L2-hot
                float4 pg = *(const float4*)&g_pre[1][off];
                float4 ci = *(const float4*)&g_c_inp[n];
                float4 cg = *(const float4*)&g_c_ig[n];
                float4 cr = *(const float4*)&g_c_rg[n];
                float4 mv = *(const float4*)&g_mem_v[n];
                float4 o1, o2;
                o1.x = sigf(pi.x + ci.x) * sigf(pg.x + cg.x);
                o1.y = sigf(pi.y + ci.y) * sigf(pg.y + cg.y);
                o1.z = sigf(pi.z + ci.z) * sigf(pg.z + cg.z);
                o1.w = sigf(pi.w + ci.w) * sigf(pg.w + cg.w);
                o2.x = sigf(pr.x + cr.x) * mv.x;
                o2.y = sigf(pr.y + cr.y) * mv.y;
                o2.z = sigf(pr.z + cr.z) * mv.z;
                o2.w = sigf(pr.w + cr.w) * mv.w;
                *(float4*)&g_pre[0][off] = o1;    // prod -> decoder addm
                *(float4*)&g_rgm[off]    = o2;    // decoder A operand
            }
            __syncthreads();
        }
    }
}

// ---------------- persistent tf32 GEMM (decoder / final split-K) ----------------
template <int MODE>
__global__ __launch_bounds__(GEMM_THREADS, 2) void k_tgemm(
    const float* __restrict__ A,
    const float* __restrict__ B0, const float* __restrict__ B1,
    float* __restrict__ C0, float* __restrict__ C1,
    int K, int lda, int ldb, int ldC, int ashift,
    int ntm, int ntn, int nmat,
    const float* __restrict__ bias, const float* __restrict__ addm)
{
    extern __shared__ float smem[];
    const uint32_t smb = smem_u32(smem);
    const int tid = threadIdx.x, wid = tid >> 5, lane = tid & 31;
    const int g = lane >> 2, t4 = lane & 3;
    const int wm = (wid >> 2) * 64, wn = (wid & 3) * 32;
    const int nc = K / KC;
    const int tpm = ntm * ntn;
    const int ntiles = nmat * tpm;

    const int ld_r0 = tid >> 3;
    const int ld_q = tid & 7;
    const int jm = lane >> 3, rr = lane & 7;
    const int hA = jm >> 1, hB = jm & 1;
    const uint32_t aRowOff = (uint32_t)(wm + (jm & 1) * 8 + rr) * 128u;
    const uint32_t bRowOff = (uint32_t)(wn + (jm >> 1) * 8 + rr) * 128u;

    for (int t = blockIdx.x; t < ntiles; t += gridDim.x) {
        const int mat = t / tpm, rem = t % tpm;
        const int m0 = (rem % ntm) * TM, n0 = (rem / ntm) * TN;
        const float* Ae = A + (size_t)mat * ashift;
        const float* B = (mat == 0) ? B0 : B1;
        float* C = (mat == 0) ? C0 : C1;

        float acc[4][4][4];
        #pragma unroll
        for (int i = 0; i < 4; i++)
            #pragma unroll
            for (int j = 0; j < 4; j++)
                #pragma unroll
                for (int q = 0; q < 4; q++) acc[i][j][q] = 0.f;

        auto issue = [&](int k0, int buf) {
            uint32_t ab = smb + buf * CH_BYTES;
            uint32_t bb = smb + (3 + buf) * CH_BYTES;
            #pragma unroll
            for (int j = 0; j < 4; j++) {
                int r = ld_r0 + j * 32;
                uint32_t dst = (uint32_t)((r * 8 + (ld_q ^ (r & 7))) * 16);
                cp16(ab + dst, Ae + (size_t)(m0 + r) * lda + k0 + ld_q * 4);
                cp16(bb + dst, B + (size_t)(n0 + r) * ldb + k0 + ld_q * 4);
            }
            CP_COMMIT();
        };
        auto compute = [&](int buf) {
            const uint32_t abase = smb + buf * CH_BYTES + aRowOff;
            const uint32_t bbase = smb + (3 + buf) * CH_BYTES + bRowOff;
            #pragma unroll
            for (int ks = 0; ks < 4; ks++) {
                const uint32_t qa = (uint32_t)(((2 * ks + hA) ^ rr) << 4);
                const uint32_t qb = (uint32_t)(((2 * ks + hB) ^ rr) << 4);
                uint32_t af[4][4], bf[8];
                #pragma unroll
                for (int mt = 0; mt < 4; mt++)
                    ldsm4(af[mt], abase + (uint32_t)(mt * 2048) + qa);
                ldsm4(bf,     bbase + qb);
                ldsm4(bf + 4, bbase + 2048u + qb);
                #pragma unroll
                for (int mt = 0; mt < 4; mt++)
                    #pragma unroll
                    for (int nt = 0; nt < 4; nt++)
                        mma1688(acc[mt][nt], af[mt], bf + nt * 2);
            }
        };

        issue(0, 0);
        issue(KC, 1);
        for (int c = 0; c < nc; c++) {
            CP_WAIT(1);
            __syncthreads();
            if (c + 2 < nc) issue((c + 2) * KC, (c + 2) % 3);
            compute(c % 3);
        }
        __syncthreads();

        float* stg = smem;
        #pragma unroll
        for (int mt = 0; mt < 4; mt++) {
            #pragma unroll
            for (int nt = 0; nt < 4; nt++) {
                int rrow = wm + mt * 16 + g;
                int cc = wn + nt * 8 + t4 * 2;
                *(float2*)(stg + rrow * 132 + cc)       = make_float2(acc[mt][nt][0], acc[mt][nt][1]);
                *(float2*)(stg + (rrow + 8) * 132 + cc) = make_float2(acc[mt][nt][2], acc[mt][nt][3]);
            }
        }
        __syncthreads();
        #pragma unroll
        for (int j = 0; j < 16; j++) {
            int s = j * GEMM_THREADS + tid;
            int r = s >> 5, cq = s & 31;
            int m = m0 + r, n = n0 + cq * 4;
            float4 v = *(float4*)(stg + r * 132 + cq * 4);
            if (MODE == 1) {
                const float4 bv = *(const float4*)(bias + n);
                const float4 av = *(const float4*)(addm + (size_t)m * ldC + n);
                v.x += bv.x + av.x; v.y += bv.y + av.y;
                v.z += bv.z + av.z; v.w += bv.w + av.w;
            }
            *(float4*)(C + (size_t)m * ldC + n) = v;
        }
        __syncthreads();
    }
}

// ---------------- split-K reduction: dout = part0 + part1 ----------------
__global__ void k_reduce(const float4* __restrict__ a, const float4* __restrict__ b,
                         float4* __restrict__ o) {
    int i = blockIdx.x * blockDim.x + threadIdx.x;
    float4 x = a[i], y = b[i];
    x.x += y.x; x.y += y.y; x.z += y.z; x.w += y.w;
    o[i] = x;
}

// ---------------- launch ----------------
extern "C" void kernel_launch(void* const* d_in, const int* in_sizes, int n_in,
                              void* d_out, int out_size) {
    P p;
    const float** f = (const float**)&p;
    for (int i = 0; i < 28; i++) f[i] = (const float*)d_in[i];

    float *pre, *rgm, *hid;
    cudaGetSymbolAddress((void**)&pre, g_pre);
    cudaGetSymbolAddress((void**)&rgm, g_rgm);
    cudaGetSymbolAddress((void**)&hid, g_hid);
    float* pre0 = pre;
    float* pre1 = pre + (size_t)BATCH * HID;
    float* pre2 = pre + (size_t)2 * BATCH * HID;

    static cudaStream_t s2 = nullptr;
    static cudaEvent_t e0 = nullptr, e2 = nullptr;
    if (s2 == nullptr) {
        cudaStreamCreateWithFlags(&s2, cudaStreamNonBlocking);
        cudaEventCreateWithFlags(&e0, cudaEventDisableTiming);
        cudaEventCreateWithFlags(&e2, cudaEventDisableTiming);
    }

    cudaFuncSetAttribute(k_s1,       cudaFuncAttributeMaxDynamicSharedMemorySize, SMEM_BYTES_G);
    cudaFuncSetAttribute(k_tgemm<0>, cudaFuncAttributeMaxDynamicSharedMemorySize, SMEM_BYTES_G);
    cudaFuncSetAttribute(k_tgemm<1>, cudaFuncAttributeMaxDynamicSharedMemorySize, SMEM_BYTES_G);

    // main: reset flag -> (e0) -> recurrence
    k_reset<<<1, 32>>>();
    cudaEventRecord(e0, 0);
    k_vec<<<VB, VTHREADS>>>(p);

    // s2: transpose (overlaps recurrence) -> after reset -> fused stage-1 + gate
    k_transpose<<<dim3(BATCH / 32, IN_DIM / 32), dim3(32, 8), 0, s2>>>(p.input);
    cudaStreamWaitEvent(s2, e0, 0);
    k_s1<<<256, GEMM_THREADS, SMEM_BYTES_G, s2>>>(p);
    cudaEventRecord(e2, s2);

    // join: decoder needs rgm/prod (e2) + k_vec (main order)
    cudaStreamWaitEvent(0, e2, 0);

    // decoder: hid[B,1024] = rgm @ W_dec^T + b_dec + prod  (256 tiles, K=1024)
    k_tgemm<1><<<GEMM_GRID, GEMM_THREADS, SMEM_BYTES_G>>>(
        rgm, p.W_dec, nullptr, hid, nullptr,
        MEMD, MEMD, MEMD, HID, 0,
        BATCH / TM, HID / TN, 1, p.b_dec, pre0);

    // final split-K=2 into scratch pre1/pre2 (dead after fused gate)
    k_tgemm<0><<<GEMM_GRID, GEMM_THREADS, SMEM_BYTES_G>>>(
        hid, p.w_ho, p.w_ho + 512, pre1, pre2,
        512, HID, HID, OUTD, 512,
        BATCH / TM, OUTD / TN, 2, nullptr, nullptr);

    // dout = part0 + part1
    k_reduce<<<(BATCH * OUTD / 4) / 256, 256>>>(
        (const float4*)pre1, (const float4*)pre2, (float4*)d_out);
}

// round 17
// speedup vs baseline: 1.1595x; 1.1595x over previous
#include <cuda_runtime.h>
#include <math.h>
#include <stdint.h>

#define IN_DIM 512
#define HID    1024
#define MEMD   1024
#define OUTD   512
#define BATCH  4096

#define TM 128
#define TN 128
#define KC 32
#define GEMM_THREADS 256
#define CH_FLOATS (128 * 32)
#define CH_BYTES  (CH_FLOATS * 4)            // 16384
#define SMEM_BYTES_G (6 * CH_BYTES)          // 98304, 2 CTAs/SM
#define GEMM_GRID 296

#define VB 64                                // recurrence blocks (own barrier)
#define VTHREADS 256

// ---------------- device scratch ----------------
__device__ __align__(16) float g_xT [(size_t)BATCH * IN_DIM];
__device__ __align__(16) float g_pre[3][(size_t)BATCH * HID];
__device__ __align__(16) float g_rgm[(size_t)BATCH * MEMD];
__device__ __align__(16) float g_hid[(size_t)BATCH * HID];

// vector state
__device__ __align__(16) float g_out_v[OUTD];
__device__ __align__(16) float g_mem_v[MEMD];
__device__ __align__(16) float g_prod_v[HID];
__device__ __align__(16) float g_rgmem_v[MEMD];
__device__ __align__(16) float g_wg_v[MEMD];
__device__ __align__(16) float g_hid_v[HID];
__device__ __align__(16) float g_c_inp[HID];
__device__ __align__(16) float g_c_ig[HID];
__device__ __align__(16) float g_c_rg[MEMD];

// software grid barrier for k_vec (g_cnt returns to 0; g_gen monotonic)
__device__ unsigned g_cnt = 0;
__device__ unsigned g_gen = 0;
__device__ unsigned g_tile = 0;              // stage-1 dynamic tile counter (reset each replay)

struct P {
    const float *input;
    const float *W_ig, *b_ig, *W_rig, *b_rig, *W_mig, *b_mig;
    const float *W_inp, *b_inp, *W_rinp, *b_rinp;
    const float *W_rg, *b_rg, *W_rrg, *b_rrg, *W_mrg, *b_mrg;
    const float *W_dec, *b_dec;
    const float *W_wg, *b_wg, *W_rwg, *b_rwg, *W_mwg, *b_mwg;
    const float *W_enc, *b_enc, *w_ho;
};

// ---- fast activations: HW tanh.approx ----
__device__ __forceinline__ float tanh_ap(float x) {
    float y;
    asm("tanh.approx.f32 %0, %1;" : "=f"(y) : "f"(x));
    return y;
}
__device__ __forceinline__ float sigf(float x) {
    return fmaf(0.5f, tanh_ap(0.5f * x), 0.5f);
}
__device__ __forceinline__ float warp_sum(float v) {
    #pragma unroll
    for (int o = 16; o; o >>= 1) v += __shfl_xor_sync(0xFFFFFFFFu, v, o);
    return v;
}
__device__ __forceinline__ float dot4(float4 a, float4 b) {
    return a.x * b.x + a.y * b.y + a.z * b.z + a.w * b.w;
}

__device__ __forceinline__ void mma1688(float* c, const uint32_t* a, const uint32_t* b) {
    asm volatile(
        "mma.sync.aligned.m16n8k8.row.col.f32.tf32.tf32.f32 "
        "{%0,%1,%2,%3}, {%4,%5,%6,%7}, {%8,%9}, {%0,%1,%2,%3};"
        : "+f"(c[0]), "+f"(c[1]), "+f"(c[2]), "+f"(c[3])
        : "r"(a[0]), "r"(a[1]), "r"(a[2]), "r"(a[3]), "r"(b[0]), "r"(b[1]));
}
__device__ __forceinline__ void ldsm4(uint32_t* r, uint32_t addr) {
    asm volatile("ldmatrix.sync.aligned.m8n8.x4.shared.b16 {%0,%1,%2,%3}, [%4];"
        : "=r"(r[0]), "=r"(r[1]), "=r"(r[2]), "=r"(r[3]) : "r"(addr));
}
__device__ __forceinline__ void cp16(uint32_t dst, const void* src) {
    asm volatile("cp.async.cg.shared.global [%0], [%1], 16;" :: "r"(dst), "l"(src));
}
#define CP_COMMIT() asm volatile("cp.async.commit_group;" ::: "memory")
#define CP_WAIT(n)  asm volatile("cp.async.wait_group %0;" :: "n"(n) : "memory")
__device__ __forceinline__ uint32_t smem_u32(const void* p) {
    uint32_t a;
    asm("{ .reg .u64 t; cvta.to.shared.u64 t, %1; cvt.u32.u64 %0, t; }" : "=r"(a) : "l"(p));
    return a;
}

// ---------------- grid barrier over VB co-resident blocks ----------------
__device__ __forceinline__ void gsync(unsigned* mygen) {
    __syncthreads();
    if (threadIdx.x == 0) {
        __threadfence();
        unsigned a = atomicAdd(&g_cnt, 1);
        if (a == VB - 1) {
            g_cnt = 0;
            __threadfence();
            atomicAdd(&g_gen, 1);
        } else {
            while (*(volatile unsigned*)&g_gen == *mygen) __nanosleep(64);
        }
        __threadfence();
    }
    __syncthreads();
    (*mygen)++;
}

// ---------------- reset: stage-1 tile counter (strictly before stage-1) ----------------
__global__ void k_reset() {
    if (threadIdx.x == 0) g_tile = 0;
}

// ---------------- transpose: input [512,4096] -> g_xT [4096,512] ----------------
__global__ void k_transpose(const float* __restrict__ in) {
    __shared__ float t[32][33];
    int bx = blockIdx.x * 32;
    int by = blockIdx.y * 32;
    for (int j = threadIdx.y; j < 32; j += 8)
        t[j][threadIdx.x] = in[(size_t)(by + j) * BATCH + bx + threadIdx.x];
    __syncthreads();
    for (int j = threadIdx.y; j < 32; j += 8)
        g_xT[(size_t)(bx + j) * IN_DIM + by + threadIdx.x] = t[threadIdx.x][j];
}

// ---------------- persistent vector recurrence (VB blocks; runs ∥ stage-1) ----------------
__global__ __launch_bounds__(VTHREADS) void k_vec(P p) {
    const int tid = threadIdx.x, wid = tid >> 5, lane = tid & 31;
    const int gw = blockIdx.x * (VTHREADS / 32) + wid;
    const int VW = VB * (VTHREADS / 32);
    unsigned mygen = *(volatile unsigned*)&g_gen;

    // ---- step 0 elementwise: out=mem=0 -> gates are bias-only ----
    for (int h = blockIdx.x * VTHREADS + tid; h < HID; h += VB * VTHREADS) {
        float pbi = p.b_inp[h] + p.b_rinp[h];
        float pig = p.b_ig[h] + p.b_mig[h] + p.b_rig[h];
        float pwg = p.b_wg[h] + p.b_mwg[h] + p.b_rwg[h];
        __stcg(&g_hid_v[h], p.b_dec[h] + sigf(pbi) * sigf(pig));
        __stcg(&g_wg_v[h], sigf(pwg));
    }
    gsync(&mygen);

    auto do_update = [&](bool first) {
        for (int r = gw; r < MEMD + OUTD; r += VW) {
            const float* W = (r < MEMD) ? (p.W_enc + (size_t)r * HID)
                                        : (p.w_ho + (size_t)(r - MEMD) * HID);
            float s = 0.f;
            #pragma unroll
            for (int j = 0; j < 8; j++) {
                int k = lane + j * 32;
                float4 hv = __ldcg((const float4*)g_hid_v + k);
                s += dot4(hv, *((const float4*)W + k));
            }
            s = warp_sum(s);
            if (lane == 0) {
                if (r < MEMD) {
                    float e = tanh_ap(s + p.b_enc[r]);
                    float w = __ldcg(&g_wg_v[r]);
                    float m = first ? (w * e) : ((1.0f - w) * __ldcg(&g_mem_v[r]) + w * e);
                    __stcg(&g_mem_v[r], m);
                } else {
                    __stcg(&g_out_v[r - MEMD], s);
                }
            }
        }
    };

    do_update(true);
    gsync(&mygen);

    auto do_gates = [&](bool constants) {
        for (int h = gw; h < HID; h += VW) {
            const float4* Wbi = (const float4*)(p.W_rinp + (size_t)h * OUTD);
            const float4* Wig = (const float4*)(p.W_rig  + (size_t)h * OUTD);
            const float4* Wrg = (const float4*)(p.W_rrg  + (size_t)h * OUTD);
            const float4* Wwg = (const float4*)(p.W_rwg  + (size_t)h * OUTD);
            const float4* Mig = (const float4*)(p.W_mig  + (size_t)h * MEMD);
            const float4* Mrg = (const float4*)(p.W_mrg  + (size_t)h * MEMD);
            const float4* Mwg = (const float4*)(p.W_mwg  + (size_t)h * MEMD);
            float s_bi = 0.f, s_ig = 0.f, s_rg = 0.f, s_wg = 0.f;
            #pragma unroll
            for (int j = 0; j < 4; j++) {
                int k = lane + j * 32;
                float4 o = __ldcg((const float4*)g_out_v + k);
                s_bi += dot4(o, Wbi[k]);
                s_ig += dot4(o, Wig[k]);
                s_rg += dot4(o, Wrg[k]);
                if (!constants) s_wg += dot4(o, Wwg[k]);
            }
            #pragma unroll
            for (int j = 0; j < 8; j++) {
                int k = lane + j * 32;
                float4 m = __ldcg((const float4*)g_mem_v + k);
                s_ig += dot4(m, Mig[k]);
                s_rg += dot4(m, Mrg[k]);
                if (!constants) s_wg += dot4(m, Mwg[k]);
            }
            s_bi = warp_sum(s_bi); s_ig = warp_sum(s_ig); s_rg = warp_sum(s_rg);
            if (!constants) s_wg = warp_sum(s_wg);
            if (lane == 0) {
                float pbi = s_bi + p.b_inp[h] + p.b_rinp[h];
                float pig = s_ig + p.b_ig[h] + p.b_mig[h] + p.b_rig[h];
                float prg = s_rg + p.b_rg[h] + p.b_mrg[h] + p.b_rrg[h];
                if (!constants) {
                    float pwg = s_wg + p.b_wg[h] + p.b_mwg[h] + p.b_rwg[h];
                    __stcg(&g_prod_v[h],  sigf(pbi) * sigf(pig));
                    __stcg(&g_rgmem_v[h], sigf(prg) * __ldcg(&g_mem_v[h]));
                    __stcg(&g_wg_v[h],    sigf(pwg));
                } else {
                    __stcg(&g_c_inp[h], pbi);
                    __stcg(&g_c_ig[h],  pig);
                    __stcg(&g_c_rg[h],  prg);
                }
            }
        }
    };

    for (int s = 1; s <= 3; s++) {
        do_gates(false);
        gsync(&mygen);
        for (int h = gw; h < HID; h += VW) {
            const float4* Wd = (const float4*)(p.W_dec + (size_t)h * MEMD);
            float s2 = 0.f;
            #pragma unroll
            for (int j = 0; j < 8; j++) {
                int k = lane + j * 32;
                float4 rg = __ldcg((const float4*)g_rgmem_v + k);
                s2 += dot4(rg, Wd[k]);
            }
            s2 = warp_sum(s2);
            if (lane == 0)
                __stcg(&g_hid_v[h], s2 + p.b_dec[h] + __ldcg(&g_prod_v[h]));
        }
        gsync(&mygen);
        do_update(false);
        gsync(&mygen);
    }

    do_gates(true);   // step-4 batch-uniform constants
}

// ---------------- tf32 GEMM: 3-stage cp.async + ldmatrix; static stride or dynamic queue ----------------
// C[M,N] = A[M, kwin] @ B[N, kwin]^T; lda/ldb full row strides; A += mat*ashift (split-K).
template <int MODE, int DYN>
__global__ __launch_bounds__(GEMM_THREADS, 2) void k_tgemm(
    const float* __restrict__ A,
    const float* __restrict__ B0, const float* __restrict__ B1, const float* __restrict__ B2,
    float* __restrict__ C0, float* __restrict__ C1, float* __restrict__ C2,
    int K, int lda, int ldb, int ldC, int ashift,
    int ntm, int ntn, int nmat,
    const float* __restrict__ bias, const float* __restrict__ addm)
{
    extern __shared__ float smem[];
    __shared__ unsigned s_t;
    const uint32_t smb = smem_u32(smem);
    const int tid = threadIdx.x, wid = tid >> 5, lane = tid & 31;
    const int g = lane >> 2, t4 = lane & 3;
    const int wm = (wid >> 2) * 64, wn = (wid & 3) * 32;
    const int nc = K / KC;
    const int tpm = ntm * ntn;
    const int ntiles = nmat * tpm;

    const int ld_r0 = tid >> 3;
    const int ld_q = tid & 7;
    const int jm = lane >> 3, rr = lane & 7;
    const int hA = jm >> 1, hB = jm & 1;
    const uint32_t aRowOff = (uint32_t)(wm + (jm & 1) * 8 + rr) * 128u;
    const uint32_t bRowOff = (uint32_t)(wn + (jm >> 1) * 8 + rr) * 128u;

    int t = blockIdx.x;
    for (;;) {
        if (DYN) {
            if (tid == 0) s_t = atomicAdd(&g_tile, 1);
            __syncthreads();
            t = (int)s_t;
        }
        if (t >= ntiles) break;

        const int mat = t / tpm, rem = t % tpm;
        const int m0 = (rem % ntm) * TM, n0 = (rem / ntm) * TN;
        const float* Ae = A + (size_t)mat * ashift;
        const float* B = (mat == 0) ? B0 : ((mat == 1) ? B1 : B2);
        float* C = (mat == 0) ? C0 : ((mat == 1) ? C1 : C2);

        float acc[4][4][4];
        #pragma unroll
        for (int i = 0; i < 4; i++)
            #pragma unroll
            for (int j = 0; j < 4; j++)
                #pragma unroll
                for (int q = 0; q < 4; q++) acc[i][j][q] = 0.f;

        auto issue = [&](int k0, int buf) {
            uint32_t ab = smb + buf * CH_BYTES;
            uint32_t bb = smb + (3 + buf) * CH_BYTES;
            #pragma unroll
            for (int j = 0; j < 4; j++) {
                int r = ld_r0 + j * 32;
                uint32_t dst = (uint32_t)((r * 8 + (ld_q ^ (r & 7))) * 16);
                cp16(ab + dst, Ae + (size_t)(m0 + r) * lda + k0 + ld_q * 4);
                cp16(bb + dst, B + (size_t)(n0 + r) * ldb + k0 + ld_q * 4);
            }
            CP_COMMIT();
        };
        auto compute = [&](int buf) {
            const uint32_t abase = smb + buf * CH_BYTES + aRowOff;
            const uint32_t bbase = smb + (3 + buf) * CH_BYTES + bRowOff;
            #pragma unroll
            for (int ks = 0; ks < 4; ks++) {
                const uint32_t qa = (uint32_t)(((2 * ks + hA) ^ rr) << 4);
                const uint32_t qb = (uint32_t)(((2 * ks + hB) ^ rr) << 4);
                uint32_t af[4][4], bf[8];
                #pragma unroll
                for (int mt = 0; mt < 4; mt++)
                    ldsm4(af[mt], abase + (uint32_t)(mt * 2048) + qa);
                ldsm4(bf,     bbase + qb);
                ldsm4(bf + 4, bbase + 2048u + qb);
                #pragma unroll
                for (int mt = 0; mt < 4; mt++)
                    #pragma unroll
                    for (int nt = 0; nt < 4; nt++)
                        mma1688(acc[mt][nt], af[mt], bf + nt * 2);
            }
        };

        issue(0, 0);
        issue(KC, 1);
        for (int c = 0; c < nc; c++) {
            CP_WAIT(1);
            __syncthreads();
            if (c + 2 < nc) issue((c + 2) * KC, (c + 2) % 3);
            compute(c % 3);
        }
        __syncthreads();

        // ---- epilogue ----
        float* stg = smem;
        #pragma unroll
        for (int mt = 0; mt < 4; mt++) {
            #pragma unroll
            for (int nt = 0; nt < 4; nt++) {
                int rrow = wm + mt * 16 + g;
                int cc = wn + nt * 8 + t4 * 2;
                *(float2*)(stg + rrow * 132 + cc)       = make_float2(acc[mt][nt][0], acc[mt][nt][1]);
                *(float2*)(stg + (rrow + 8) * 132 + cc) = make_float2(acc[mt][nt][2], acc[mt][nt][3]);
            }
        }
        __syncthreads();
        #pragma unroll
        for (int j = 0; j < 16; j++) {
            int s = j * GEMM_THREADS + tid;
            int r = s >> 5, cq = s & 31;
            int m = m0 + r, n = n0 + cq * 4;
            float4 v = *(float4*)(stg + r * 132 + cq * 4);
            if (MODE == 1) {
                const float4 bv = *(const float4*)(bias + n);
                const float4 av = *(const float4*)(addm + (size_t)m * ldC + n);
                v.x += bv.x + av.x; v.y += bv.y + av.y;
                v.z += bv.z + av.z; v.w += bv.w + av.w;
            }
            *(float4*)(C + (size_t)m * ldC + n) = v;
        }
        __syncthreads();

        if (!DYN) {
            t += gridDim.x;
            if (t >= ntiles) break;
        }
    }
}

// ---------------- fused gate elementwise (step 4), [B, F] layout ----------------
__global__ void k_gate_elem() {
    size_t idx = ((size_t)blockIdx.x * blockDim.x + threadIdx.x) * 4;
    int h = (int)(idx & (HID - 1));
    float4 ci = *(const float4*)&g_c_inp[h];
    float4 cg = *(const float4*)&g_c_ig[h];
    float4 cr = *(const float4*)&g_c_rg[h];
    float4 mv = *(const float4*)&g_mem_v[h];
    float4 pi = *(const float4*)&g_pre[0][idx];
    float4 pg = *(const float4*)&g_pre[1][idx];
    float4 pr = *(const float4*)&g_pre[2][idx];
    float4 o1, o2;
    o1.x = sigf(pi.x + ci.x) * sigf(pg.x + cg.x);
    o1.y = sigf(pi.y + ci.y) * sigf(pg.y + cg.y);
    o1.z = sigf(pi.z + ci.z) * sigf(pg.z + cg.z);
    o1.w = sigf(pi.w + ci.w) * sigf(pg.w + cg.w);
    o2.x = sigf(pr.x + cr.x) * mv.x;
    o2.y = sigf(pr.y + cr.y) * mv.y;
    o2.z = sigf(pr.z + cr.z) * mv.z;
    o2.w = sigf(pr.w + cr.w) * mv.w;
    *(float4*)&g_pre[0][idx] = o1;   // prod -> addm for decoder epilogue
    *(float4*)&g_rgm[idx]    = o2;   // decoder A operand
}

// ---------------- split-K reduction: dout = part0 + part1 ----------------
__global__ void k_reduce(const float4* __restrict__ a, const float4* __restrict__ b,
                         float4* __restrict__ o) {
    int i = blockIdx.x * blockDim.x + threadIdx.x;
    float4 x = a[i], y = b[i];
    x.x += y.x; x.y += y.y; x.z += y.z; x.w += y.w;
    o[i] = x;
}

// ---------------- launch ----------------
extern "C" void kernel_launch(void* const* d_in, const int* in_sizes, int n_in,
                              void* d_out, int out_size) {
    P p;
    const float** f = (const float**)&p;
    for (int i = 0; i < 28; i++) f[i] = (const float*)d_in[i];

    float *xT, *pre, *rgm, *hid;
    cudaGetSymbolAddress((void**)&xT,  g_xT);
    cudaGetSymbolAddress((void**)&pre, g_pre);
    cudaGetSymbolAddress((void**)&rgm, g_rgm);
    cudaGetSymbolAddress((void**)&hid, g_hid);
    float* pre0 = pre;
    float* pre1 = pre + (size_t)BATCH * HID;
    float* pre2 = pre + (size_t)2 * BATCH * HID;

    static cudaStream_t s2 = nullptr;
    static cudaEvent_t e0 = nullptr, e2 = nullptr;
    if (s2 == nullptr) {
        cudaStreamCreateWithFlags(&s2, cudaStreamNonBlocking);
        cudaEventCreateWithFlags(&e0, cudaEventDisableTiming);
        cudaEventCreateWithFlags(&e2, cudaEventDisableTiming);
    }

    cudaFuncSetAttribute(k_tgemm<0,0>, cudaFuncAttributeMaxDynamicSharedMemorySize, SMEM_BYTES_G);
    cudaFuncSetAttribute(k_tgemm<0,1>, cudaFuncAttributeMaxDynamicSharedMemorySize, SMEM_BYTES_G);
    cudaFuncSetAttribute(k_tgemm<1,0>, cudaFuncAttributeMaxDynamicSharedMemorySize, SMEM_BYTES_G);

    // main: reset tile counter -> (e0) -> recurrence (places its 64 blocks first)
    k_reset<<<1, 32>>>();
    cudaEventRecord(e0, 0);
    k_vec<<<VB, VTHREADS>>>(p);

    // s2: transpose (overlaps recurrence), then stage-1 with dynamic tile queue
    k_transpose<<<dim3(BATCH / 32, IN_DIM / 32), dim3(32, 8), 0, s2>>>(p.input);
    cudaStreamWaitEvent(s2, e0, 0);
    k_tgemm<0,1><<<GEMM_GRID, GEMM_THREADS, SMEM_BYTES_G, s2>>>(
        xT, p.W_inp, p.W_ig, p.W_rg, pre0, pre1, pre2,
        IN_DIM, IN_DIM, IN_DIM, HID, 0,
        BATCH / TM, HID / TN, 3, nullptr, nullptr);
    cudaEventRecord(e2, s2);

    // join: gate needs stage-1 (e2) + recurrence constants (main-stream order)
    cudaStreamWaitEvent(0, e2, 0);

    // gate
    k_gate_elem<<<(int)(((size_t)BATCH * HID / 4) / 256), 256>>>();

    // decoder: hid[B,1024] = rgm @ W_dec^T + b_dec + prod  (256 tiles, K=1024)
    k_tgemm<1,0><<<GEMM_GRID, GEMM_THREADS, SMEM_BYTES_G>>>(
        rgm, p.W_dec, nullptr, nullptr, hid, nullptr, nullptr,
        MEMD, MEMD, MEMD, HID, 0,
        BATCH / TM, HID / TN, 1, p.b_dec, pre0);

    // final split-K=2 into scratch pre1/pre2 (dead after gate)
    k_tgemm<0,0><<<GEMM_GRID, GEMM_THREADS, SMEM_BYTES_G>>>(
        hid, p.w_ho, p.w_ho + 512, nullptr, pre1, pre2, nullptr,
        512, HID, HID, OUTD, 512,
        BATCH / TM, OUTD / TN, 2, nullptr, nullptr);

    // dout = part0 + part1
    k_reduce<<<(BATCH * OUTD / 4) / 256, 256>>>(
        (const float4*)pre1, (const float4*)pre2, (float4*)d_out);
}